// round 16
// baseline (speedup 1.0000x reference)
#include <cuda_runtime.h>
#include <cuda_fp16.h>
#include <cstdint>

// ---------------------------------------------------------------------------
// G2Conv2d4, fp16 mma.sync m16n8k16 (Round 16: bisect round).
// Pre-pass = EXACT Round-12 kernels (proven: rel_err 2.99e-4):
//   energy_argmax (512 blocks) -> pool (x^2 -> fp16, B-frag ci' permute)
//   -> wprep (fragment-major fp16 weights).
// Conv = Round-13's 2-row-strip version (grid 1024 = 6.92 waves, 98.8% chip
// utilization vs 86.5% at 512 CTAs). CTA: 128co x 2rows x 64px, 512 thr,
// warp tile 32co x 32px; cp.async double-buffered, all 9 taps resident.
// ---------------------------------------------------------------------------

__device__ unsigned long long g_part[512];                    // argmax partials
__device__ __align__(16) __half g_pt[16ull * 64 * 64 * 256];  // pooled 33.5MB
__device__ __align__(16) uint32_t g_wf[9 * 16 * 16 * 32 * 4]; // frag-major w

__device__ __forceinline__ uint32_t smem_u32(const void* p) {
    uint32_t a;
    asm("{ .reg .u64 t; cvta.to.shared.u64 t, %1; cvt.u32.u64 %0, t; }"
        : "=r"(a) : "l"(p));
    return a;
}

#define LDS128U(r, addr)                                                      \
    asm volatile("ld.shared.v4.b32 {%0,%1,%2,%3}, [%4];"                      \
                 : "=r"((r)[0]), "=r"((r)[1]), "=r"((r)[2]), "=r"((r)[3])     \
                 : "r"(addr))
#define MMA_F16(d, a, b0, b1)                                                 \
    asm volatile(                                                             \
        "mma.sync.aligned.m16n8k16.row.col.f32.f16.f16.f32 "                  \
        "{%0,%1,%2,%3}, {%4,%5,%6,%7}, {%8,%9}, {%0,%1,%2,%3};"               \
        : "+f"((d)[0]), "+f"((d)[1]), "+f"((d)[2]), "+f"((d)[3])              \
        : "r"((a)[0]), "r"((a)[1]), "r"((a)[2]), "r"((a)[3]),                 \
          "r"(b0), "r"(b1))
#define CP16(dst, src, sz)                                                    \
    asm volatile("cp.async.cg.shared.global [%0], [%1], 16, %2;"              \
                 :: "r"(dst), "l"(src), "r"(sz))
#define CP_COMMIT() asm volatile("cp.async.commit_group;" ::: "memory")
#define CP_WAIT0()  asm volatile("cp.async.wait_group 0;" ::: "memory")

// ---------------- Kernel 1: energy argmax partials (R12 verbatim) --------
__global__ void energy_argmax_kernel(const float* __restrict__ x) {
    int bq    = blockIdx.x >> 3;
    int slice = blockIdx.x & 7;
    int b = bq >> 2, q = bq & 3;
    const float* xb = x + (((size_t)b * 256 + q * 64) << 12);

    unsigned long long best = 0ull;
    int p0 = slice * 512;
    for (int p = p0 + threadIdx.x; p < p0 + 512; p += 256) {
        float s = 0.0f;
#pragma unroll 8
        for (int c = 0; c < 64; ++c) {
            float v = xb[((size_t)c << 12) + p];
            s = fmaf(v, v, s);
        }
        unsigned long long key =
            ((unsigned long long)__float_as_uint(s) << 32) |
            (unsigned long long)(unsigned)(~p);
        if (key > best) best = key;
    }
    __shared__ unsigned long long sk[256];
    sk[threadIdx.x] = best;
    __syncthreads();
    for (int off = 128; off; off >>= 1) {
        if (threadIdx.x < off) {
            unsigned long long o = sk[threadIdx.x + off];
            if (o > sk[threadIdx.x]) sk[threadIdx.x] = o;
        }
        __syncthreads();
    }
    if (threadIdx.x == 0) g_part[blockIdx.x] = sk[0];
}

// ---------------- Kernel 2: pooled x^2 -> fp16 (R12 verbatim) ------------
// layout: [pixel*256 + ci'], ci' within each 32-group:
//   pos(j) = 8*((j&7)>>1) + 4*(j>>4) + 2*((j&15)>>3) + (j&1)
__global__ void pool_kernel(const float* __restrict__ x) {
    int bid = blockIdx.x;              // b*64 + y
    int b = bid >> 6, y = bid & 63;
    int ci = threadIdx.x;
    int q = ci >> 6;
    int bq = (b << 2) | q;

    unsigned long long key = 0ull;
#pragma unroll
    for (int s = 0; s < 8; ++s) {
        unsigned long long o = g_part[bq * 8 + s];
        if (o > key) key = o;
    }
    int p = (int)(~(unsigned)key) & 4095;
    int r = p >> 6, c = p & 63;

    const float* xc = x + ((size_t)(b * 256 + ci) << 12);
    float lv = xc[(r << 6) | c];
    lv *= lv;
    bool ch = (q < 2) ? (y <= r) : (y >= r);
    bool leftW = ((q & 1) == 0);

    int j = ci & 31;
    int pos = 8 * ((j & 7) >> 1) + 4 * (j >> 4) + 2 * ((j & 15) >> 3) + (j & 1);
    int ci_perm = (ci & ~31) + pos;

    const float4* row4 = (const float4*)(xc + (y << 6));
    size_t obase = (((size_t)bid << 6) << 8) + ci_perm;

#pragma unroll 4
    for (int i = 0; i < 16; ++i) {
        float4 v = row4[i];
        int x0 = i << 2;
        float s[4] = {v.x * v.x, v.y * v.y, v.z * v.z, v.w * v.w};
        if (ch) {
#pragma unroll
            for (int jj = 0; jj < 4; ++jj)
                if (leftW ? (x0 + jj <= c) : (x0 + jj >= c))
                    s[jj] = fmaxf(s[jj], lv);
        }
#pragma unroll
        for (int jj = 0; jj < 4; ++jj)
            g_pt[obase + ((size_t)(x0 + jj) << 8)] = __float2half_rn(s[jj]);
    }
}

// ---------------- Kernel 3: weights -> fragment-major fp16 (R12) ---------
__global__ void wprep_kernel(const float* __restrict__ w) {
    int idx = blockIdx.x * 256 + threadIdx.x;     // 1152 blocks = 294912
    int u    = idx & 3;
    int lane = (idx >> 2) & 31;
    int ct   = (idx >> 7) & 15;
    int k16  = (idx >> 11) & 15;
    int tap  = idx >> 15;
    int co  = ct * 16 + (lane >> 2) + ((u & 1) << 3);
    int ci0 = k16 * 16 + ((lane & 3) << 1) + ((u >> 1) << 3);
    unsigned h0 = __half_as_ushort(
        __float2half_rn(w[((size_t)co * 256 + ci0) * 9 + tap]));
    unsigned h1 = __half_as_ushort(
        __float2half_rn(w[((size_t)co * 256 + ci0 + 1) * 9 + tap]));
    g_wf[idx] = (h1 << 16) | h0;
}

// ---------------- Kernel 4: fp16 mma conv (2-row CTAs, grid 1024) --------
// smem per buffer: xs[row(4)][slot(66)][64B] (16896 B)
//                  ws[tap(9)][k16(2)][ct8(8)][512B] (73728 B)
#define XS_SLOT 64
#define XS_M (66 * XS_SLOT)        // 4224
#define XS_TOT (4 * XS_M)          // 16896
#define WS_TOT 73728
#define BUF_SZ (XS_TOT + WS_TOT)   // 90624
#define SMEM_TOTAL (2 * BUF_SZ)    // 181248

__global__ __launch_bounds__(512, 1)
void conv_mma_kernel(const float* __restrict__ bias, float* __restrict__ out) {
    extern __shared__ __align__(16) char smem[];
    const uint32_t sb = smem_u32(smem);
    const int tid = threadIdx.x;
    const int wid = tid >> 5;
    const int lane = tid & 31;

    const int strip = blockIdx.x;          // 0..31 -> 2 rows each
    const int half  = blockIdx.y;          // 0..1
    const int b     = blockIdx.z;          // 0..15
    const int y0    = strip << 1;

    const int wm = wid >> 2;               // 0..3 (co 32-tile)
    const int wn = wid & 3;                // row = wn>>1, px half = (wn&1)*32
    const int row_w = wn >> 1;
    const int px_half = (wn & 1) << 5;
    const int ln4 = lane & 3, lq = lane >> 2;

    auto stage = [&](int chunk, uint32_t bufbase) {
        const int k16b = chunk * 2;
        // weights: 9 taps x 2 k16 x 8 ct8 x 32 lanes = 4608 uint4
#pragma unroll
        for (int it = 0; it < 9; ++it) {
            int idx = tid + it * 512;
            int tap = idx >> 9, rem = idx & 511;
            int k16i = rem >> 8, ct8 = (rem >> 5) & 7, ln = rem & 31;
            const uint4* g = (const uint4*)g_wf +
                ((((size_t)tap * 16 + k16b + k16i) * 16 + half * 8 + ct8) << 5) + ln;
            CP16(bufbase + XS_TOT + tap * 8192 + k16i * 4096 + ct8 * 512 + ln * 16,
                 g, 16);
        }
        // input: 4 rows x 64 px x 4 quads = 1024 uint4 (OOB rows zero-fill)
#pragma unroll
        for (int it = 0; it < 2; ++it) {
            int idx = tid + it * 512;
            int m = idx >> 8, rem = idx & 255;
            int px = rem >> 2, qq = rem & 3;
            int yi = y0 + m - 1;
            const __half* g = g_pt +
                (((size_t)b * 4096 + (yi & 63) * 64 + px) << 8) +
                chunk * 32 + qq * 8;
            int sz = ((unsigned)yi < 64u) ? 16 : 0;
            CP16(bufbase + m * XS_M + (px + 1) * XS_SLOT + qq * 16, g, sz);
        }
        CP_COMMIT();
    };

    stage(0, sb);

    // permanent zero borders (slots 0 and 65), both buffers: 64 uint4
    if (tid < 64) {
        int bf = tid >> 5, rem = tid & 31;
        int m = rem >> 3, s = (rem >> 2) & 1, qq = rem & 3;
        *(uint4*)(smem + bf * BUF_SZ + m * XS_M + (s ? 65 : 0) * XS_SLOT +
                  qq * 16) = make_uint4(0, 0, 0, 0);
    }

    float acc[2][4][4];
#pragma unroll
    for (int i = 0; i < 2; ++i)
#pragma unroll
        for (int jj = 0; jj < 4; ++jj)
#pragma unroll
            for (int k = 0; k < 4; ++k) acc[i][jj][k] = 0.0f;

#pragma unroll 1
    for (int chunk = 0; chunk < 8; ++chunk) {
        CP_WAIT0();
        __syncthreads();
        if (chunk < 7) stage(chunk + 1, sb + ((chunk + 1) & 1) * BUF_SZ);

        const uint32_t xb = sb + (chunk & 1) * BUF_SZ;
        const uint32_t wb = xb + XS_TOT;

#pragma unroll
        for (int tap = 0; tap < 9; ++tap) {
            const int dy = tap / 3, dx = tap - dy * 3;
            const uint32_t bb = xb + (row_w + dy) * XS_M +
                                (px_half + lq + dx) * XS_SLOT + ln4 * 16;
            const uint32_t ab = wb + tap * 8192 + (wm * 2) * 512 + lane * 16;

            uint32_t a[2][2][4];
#pragma unroll
            for (int ks = 0; ks < 2; ++ks)
#pragma unroll
                for (int mi = 0; mi < 2; ++mi)
                    LDS128U(a[ks][mi], ab + ks * 4096 + mi * 512);

#pragma unroll
            for (int nb = 0; nb < 4; ++nb) {
                uint32_t bq4[4];
                LDS128U(bq4, bb + nb * 512);
#pragma unroll
                for (int mi = 0; mi < 2; ++mi) {
                    MMA_F16(acc[mi][nb], a[0][mi], bq4[0], bq4[1]);
                    MMA_F16(acc[mi][nb], a[1][mi], bq4[2], bq4[3]);
                }
            }
        }
    }

    // ---- epilogue ----
#pragma unroll
    for (int mi = 0; mi < 2; ++mi) {
        int co = half * 128 + wm * 32 + mi * 16 + lq;
        float bv0 = bias[co];
        float bv1 = bias[co + 8];
        float* o0 = out + (((size_t)b * 256 + co) << 12) + ((y0 + row_w) << 6);
        float* o1 = o0 + (8 << 12);
#pragma unroll
        for (int nb = 0; nb < 4; ++nb) {
            int xp = px_half + nb * 8 + ln4 * 2;
            *(float2*)(o0 + xp) =
                make_float2(acc[mi][nb][0] + bv0, acc[mi][nb][1] + bv0);
            *(float2*)(o1 + xp) =
                make_float2(acc[mi][nb][2] + bv1, acc[mi][nb][3] + bv1);
        }
    }
}

// ---------------- launch ----------------
extern "C" void kernel_launch(void* const* d_in, const int* in_sizes, int n_in,
                              void* d_out, int out_size) {
    const float* x    = (const float*)d_in[0];
    const float* w    = (const float*)d_in[1];
    const float* bias = (const float*)d_in[2];
    float* out = (float*)d_out;

    static int smem_set = 0;
    if (!smem_set) {
        cudaFuncSetAttribute(conv_mma_kernel,
                             cudaFuncAttributeMaxDynamicSharedMemorySize,
                             SMEM_TOTAL);
        smem_set = 1;
    }

    energy_argmax_kernel<<<512, 256>>>(x);     // launch 0 (R12 proven)
    pool_kernel<<<1024, 256>>>(x);             // launch 1 (R12 proven)
    wprep_kernel<<<1152, 256>>>(w);            // launch 2 (R12 proven)

    dim3 grid(32, 2, 16);                      // 2-row strips, co halves, batch
    conv_mma_kernel<<<grid, 512, SMEM_TOTAL>>>(bias, out);   // launch 3
}

// round 17
// speedup vs baseline: 1.0434x; 1.0434x over previous
#include <cuda_runtime.h>
#include <cuda_fp16.h>
#include <cstdint>

// ---------------------------------------------------------------------------
// G2Conv2d4, fp16 mma.sync m16n8k16 (Round 17).
// Fused pre-pass (single x read): argmax partials + x^2 -> fp16 permuted
// transpose + weight prep in ONE kernel; then a rect-only __hmax2 landmark
// fixup. R15's failure was the fixup spanning only 4 uint4 (32 of the 64
// quadrant channels) -- fixed to 8 uint4 here.
// Conv: verified 2-row-strip kernel (128co x 2rows x 64px, 512 thr, 16 warps,
// warp tile 32co x 32px, cp.async double-buffered, all 9 taps resident).
// Conv is HMMA-f32-acc pipe-bound (~190us floor for mma.sync on this part).
// ---------------------------------------------------------------------------

__device__ unsigned long long g_part[256];                    // argmax partials
__device__ __align__(16) __half g_pt[16ull * 64 * 64 * 256];  // pooled 33.5MB
__device__ __align__(16) uint32_t g_wf[9 * 16 * 16 * 32 * 4]; // frag-major w

__device__ __forceinline__ uint32_t smem_u32(const void* p) {
    uint32_t a;
    asm("{ .reg .u64 t; cvta.to.shared.u64 t, %1; cvt.u32.u64 %0, t; }"
        : "=r"(a) : "l"(p));
    return a;
}
__device__ __forceinline__ uint32_t hmax2u(uint32_t a, uint32_t b) {
    __half2 r = __hmax2(*reinterpret_cast<__half2*>(&a),
                        *reinterpret_cast<__half2*>(&b));
    return *reinterpret_cast<uint32_t*>(&r);
}
__device__ __forceinline__ uint32_t packh2(float lo, float hi) {
    __half2 h = __floats2half2_rn(lo, hi);
    return *reinterpret_cast<uint32_t*>(&h);
}

#define LDS128U(r, addr)                                                      \
    asm volatile("ld.shared.v4.b32 {%0,%1,%2,%3}, [%4];"                      \
                 : "=r"((r)[0]), "=r"((r)[1]), "=r"((r)[2]), "=r"((r)[3])     \
                 : "r"(addr))
#define MMA_F16(d, a, b0, b1)                                                 \
    asm volatile(                                                             \
        "mma.sync.aligned.m16n8k16.row.col.f32.f16.f16.f32 "                  \
        "{%0,%1,%2,%3}, {%4,%5,%6,%7}, {%8,%9}, {%0,%1,%2,%3};"               \
        : "+f"((d)[0]), "+f"((d)[1]), "+f"((d)[2]), "+f"((d)[3])              \
        : "r"((a)[0]), "r"((a)[1]), "r"((a)[2]), "r"((a)[3]),                 \
          "r"(b0), "r"(b1))
#define CP16(dst, src, sz)                                                    \
    asm volatile("cp.async.cg.shared.global [%0], [%1], 16, %2;"              \
                 :: "r"(dst), "l"(src), "r"(sz))
#define CP_COMMIT() asm volatile("cp.async.commit_group;" ::: "memory")
#define CP_WAIT0()  asm volatile("cp.async.wait_group 0;" ::: "memory")

// ---------------- Kernel A: argmax + x^2->fp16 transpose + wprep ---------
// blocks 0..255: (bq, slice of 1024 px); 4 px/thread via float4 loads.
//   Writes g_pt[(b*4096+p)*256 + q*64 + g*32 + perm] (the conv B-frag ci'
//   permutation) and per-pixel quadrant-energy argmax partials.
//   Channel summation order is 0..63 sequential -> argmax bitwise identical
//   to the proven R12 pre-pass.
// blocks 256..543: weight prep (one uint4 = 4 u32 frags per thread).
__global__ void prep_kernel(const float* __restrict__ x,
                            const float* __restrict__ w) {
    if (blockIdx.x >= 256) {
        int base4 = (blockIdx.x - 256) * 256 + threadIdx.x;   // uint4 index
        int base = base4 << 2;
        int lane = (base >> 2) & 31, ct = (base >> 7) & 15;
        int k16 = (base >> 11) & 15, tap = base >> 15;
        uint32_t o[4];
#pragma unroll
        for (int u = 0; u < 4; ++u) {
            int co  = ct * 16 + (lane >> 2) + ((u & 1) << 3);
            int ci0 = k16 * 16 + ((lane & 3) << 1) + ((u >> 1) << 3);
            unsigned h0 = __half_as_ushort(
                __float2half_rn(w[((size_t)co * 256 + ci0) * 9 + tap]));
            unsigned h1 = __half_as_ushort(
                __float2half_rn(w[((size_t)co * 256 + ci0 + 1) * 9 + tap]));
            o[u] = (h1 << 16) | h0;
        }
        ((uint4*)g_wf)[base4] = make_uint4(o[0], o[1], o[2], o[3]);
        return;
    }

    int bqs = blockIdx.x;              // 0..255
    int bq = bqs >> 2, slice = bqs & 3;
    int b = bq >> 2, q = bq & 3;
    const float* xb = x + (((size_t)b * 256 + q * 64) << 12);
    int p0 = slice * 1024 + threadIdx.x * 4;

    float en[4] = {0.f, 0.f, 0.f, 0.f};

    for (int g = 0; g < 2; ++g) {
        uint32_t arr[4][16];
#pragma unroll
        for (int u = 0; u < 16; ++u) {
            float4 va = *(const float4*)(xb + (((size_t)(g * 32 + 2 * u)) << 12) + p0);
            float4 vb = *(const float4*)(xb + (((size_t)(g * 32 + 2 * u + 1)) << 12) + p0);
            float a0 = va.x * va.x, a1 = va.y * va.y,
                  a2 = va.z * va.z, a3 = va.w * va.w;
            float b0 = vb.x * vb.x, b1 = vb.y * vb.y,
                  b2 = vb.z * vb.z, b3 = vb.w * vb.w;
            en[0] = fmaf(va.x, va.x, en[0]); en[0] = fmaf(vb.x, vb.x, en[0]);
            en[1] = fmaf(va.y, va.y, en[1]); en[1] = fmaf(vb.y, vb.y, en[1]);
            en[2] = fmaf(va.z, va.z, en[2]); en[2] = fmaf(vb.z, vb.z, en[2]);
            en[3] = fmaf(va.w, va.w, en[3]); en[3] = fmaf(vb.w, vb.w, en[3]);
            int wpos = 4 * (u & 3) + (u >> 2);     // ci' permute, word level
            arr[0][wpos] = packh2(a0, b0);
            arr[1][wpos] = packh2(a1, b1);
            arr[2][wpos] = packh2(a2, b2);
            arr[3][wpos] = packh2(a3, b3);
        }
#pragma unroll
        for (int px = 0; px < 4; ++px) {
            uint4* dst = (uint4*)(g_pt + ((size_t)(b * 4096 + p0 + px) << 8)
                                  + q * 64 + g * 32);
#pragma unroll
            for (int i = 0; i < 4; ++i)
                dst[i] = make_uint4(arr[px][4 * i], arr[px][4 * i + 1],
                                    arr[px][4 * i + 2], arr[px][4 * i + 3]);
        }
    }

    unsigned long long best = 0ull;
#pragma unroll
    for (int px = 0; px < 4; ++px) {
        unsigned long long key =
            ((unsigned long long)__float_as_uint(en[px]) << 32) |
            (unsigned long long)(unsigned)(~(p0 + px));
        if (key > best) best = key;
    }
    __shared__ unsigned long long sk[256];
    sk[threadIdx.x] = best;
    __syncthreads();
    for (int off = 128; off; off >>= 1) {
        if (threadIdx.x < off) {
            unsigned long long o = sk[threadIdx.x + off];
            if (o > sk[threadIdx.x]) sk[threadIdx.x] = o;
        }
        __syncthreads();
    }
    if (threadIdx.x == 0) g_part[bqs] = sk[0];
}

// ---------------- Kernel B: rect-only landmark max fixup (FIXED) --------
// block = (bq, y); early-exit rows outside the landmark rectangle.
// FIX vs R15: a quadrant owns 64 channels = EIGHT uint4 (was 4 -> half the
// channels silently unpooled -> rel_err 0.45).
__global__ void fixup_kernel() {
    int bq = blockIdx.x >> 6, y = blockIdx.x & 63;
    int b = bq >> 2, q = bq & 3;

    unsigned long long key = 0ull;
#pragma unroll
    for (int s = 0; s < 4; ++s) {
        unsigned long long o = g_part[bq * 4 + s];
        if (o > key) key = o;
    }
    int p = (int)(~(unsigned)key) & 4095;
    int r = p >> 6, c = p & 63;

    bool inrow = (q < 2) ? (y <= r) : (y >= r);
    if (!inrow) return;
    int x_lo = (q & 1) ? c : 0;
    int x_hi = (q & 1) ? 63 : c;

    const uint4* ls = (const uint4*)(g_pt + ((size_t)(b * 4096 + p) << 8) + q * 64);
    uint4 l[8];
#pragma unroll
    for (int i = 0; i < 8; ++i) l[i] = ls[i];

    for (int px = x_lo + (int)threadIdx.x; px <= x_hi; px += 64) {
        uint4* dst = (uint4*)(g_pt + ((size_t)(b * 4096 + y * 64 + px) << 8) + q * 64);
#pragma unroll
        for (int i = 0; i < 8; ++i) {
            uint4 v = dst[i];
            v.x = hmax2u(v.x, l[i].x); v.y = hmax2u(v.y, l[i].y);
            v.z = hmax2u(v.z, l[i].z); v.w = hmax2u(v.w, l[i].w);
            dst[i] = v;
        }
    }
}

// ---------------- Kernel C: fp16 mma conv (verified, 2-row CTAs) ---------
#define XS_SLOT 64
#define XS_M (66 * XS_SLOT)        // 4224
#define XS_TOT (4 * XS_M)          // 16896
#define WS_TOT 73728
#define BUF_SZ (XS_TOT + WS_TOT)   // 90624
#define SMEM_TOTAL (2 * BUF_SZ)    // 181248

__global__ __launch_bounds__(512, 1)
void conv_mma_kernel(const float* __restrict__ bias, float* __restrict__ out) {
    extern __shared__ __align__(16) char smem[];
    const uint32_t sb = smem_u32(smem);
    const int tid = threadIdx.x;
    const int wid = tid >> 5;
    const int lane = tid & 31;

    const int strip = blockIdx.x;          // 0..31 -> 2 rows each
    const int half  = blockIdx.y;          // 0..1
    const int b     = blockIdx.z;          // 0..15
    const int y0    = strip << 1;

    const int wm = wid >> 2;               // 0..3 (co 32-tile)
    const int wn = wid & 3;                // row = wn>>1, px half = (wn&1)*32
    const int row_w = wn >> 1;
    const int px_half = (wn & 1) << 5;
    const int ln4 = lane & 3, lq = lane >> 2;

    auto stage = [&](int chunk, uint32_t bufbase) {
        const int k16b = chunk * 2;
#pragma unroll
        for (int it = 0; it < 9; ++it) {
            int idx = tid + it * 512;
            int tap = idx >> 9, rem = idx & 511;
            int k16i = rem >> 8, ct8 = (rem >> 5) & 7, ln = rem & 31;
            const uint4* g = (const uint4*)g_wf +
                ((((size_t)tap * 16 + k16b + k16i) * 16 + half * 8 + ct8) << 5) + ln;
            CP16(bufbase + XS_TOT + tap * 8192 + k16i * 4096 + ct8 * 512 + ln * 16,
                 g, 16);
        }
#pragma unroll
        for (int it = 0; it < 2; ++it) {
            int idx = tid + it * 512;
            int m = idx >> 8, rem = idx & 255;
            int px = rem >> 2, qq = rem & 3;
            int yi = y0 + m - 1;
            const __half* g = g_pt +
                (((size_t)b * 4096 + (yi & 63) * 64 + px) << 8) +
                chunk * 32 + qq * 8;
            int sz = ((unsigned)yi < 64u) ? 16 : 0;
            CP16(bufbase + m * XS_M + (px + 1) * XS_SLOT + qq * 16, g, sz);
        }
        CP_COMMIT();
    };

    stage(0, sb);

    if (tid < 64) {
        int bf = tid >> 5, rem = tid & 31;
        int m = rem >> 3, s = (rem >> 2) & 1, qq = rem & 3;
        *(uint4*)(smem + bf * BUF_SZ + m * XS_M + (s ? 65 : 0) * XS_SLOT +
                  qq * 16) = make_uint4(0, 0, 0, 0);
    }

    float acc[2][4][4];
#pragma unroll
    for (int i = 0; i < 2; ++i)
#pragma unroll
        for (int jj = 0; jj < 4; ++jj)
#pragma unroll
            for (int k = 0; k < 4; ++k) acc[i][jj][k] = 0.0f;

#pragma unroll 1
    for (int chunk = 0; chunk < 8; ++chunk) {
        CP_WAIT0();
        __syncthreads();
        if (chunk < 7) stage(chunk + 1, sb + ((chunk + 1) & 1) * BUF_SZ);

        const uint32_t xb = sb + (chunk & 1) * BUF_SZ;
        const uint32_t wb = xb + XS_TOT;

#pragma unroll
        for (int tap = 0; tap < 9; ++tap) {
            const int dy = tap / 3, dx = tap - dy * 3;
            const uint32_t bb = xb + (row_w + dy) * XS_M +
                                (px_half + lq + dx) * XS_SLOT + ln4 * 16;
            const uint32_t ab = wb + tap * 8192 + (wm * 2) * 512 + lane * 16;

            uint32_t a[2][2][4];
#pragma unroll
            for (int ks = 0; ks < 2; ++ks)
#pragma unroll
                for (int mi = 0; mi < 2; ++mi)
                    LDS128U(a[ks][mi], ab + ks * 4096 + mi * 512);

#pragma unroll
            for (int nb = 0; nb < 4; ++nb) {
                uint32_t bq4[4];
                LDS128U(bq4, bb + nb * 512);
#pragma unroll
                for (int mi = 0; mi < 2; ++mi) {
                    MMA_F16(acc[mi][nb], a[0][mi], bq4[0], bq4[1]);
                    MMA_F16(acc[mi][nb], a[1][mi], bq4[2], bq4[3]);
                }
            }
        }
    }

#pragma unroll
    for (int mi = 0; mi < 2; ++mi) {
        int co = half * 128 + wm * 32 + mi * 16 + lq;
        float bv0 = bias[co];
        float bv1 = bias[co + 8];
        float* o0 = out + (((size_t)b * 256 + co) << 12) + ((y0 + row_w) << 6);
        float* o1 = o0 + (8 << 12);
#pragma unroll
        for (int nb = 0; nb < 4; ++nb) {
            int xp = px_half + nb * 8 + ln4 * 2;
            *(float2*)(o0 + xp) =
                make_float2(acc[mi][nb][0] + bv0, acc[mi][nb][1] + bv0);
            *(float2*)(o1 + xp) =
                make_float2(acc[mi][nb][2] + bv1, acc[mi][nb][3] + bv1);
        }
    }
}

// ---------------- launch ----------------
extern "C" void kernel_launch(void* const* d_in, const int* in_sizes, int n_in,
                              void* d_out, int out_size) {
    const float* x    = (const float*)d_in[0];
    const float* w    = (const float*)d_in[1];
    const float* bias = (const float*)d_in[2];
    float* out = (float*)d_out;

    static int smem_set = 0;
    if (!smem_set) {
        cudaFuncSetAttribute(conv_mma_kernel,
                             cudaFuncAttributeMaxDynamicSharedMemorySize,
                             SMEM_TOTAL);
        smem_set = 1;
    }

    prep_kernel<<<544, 256>>>(x, w);           // argmax + x^2 transpose + wprep
    fixup_kernel<<<4096, 64>>>();              // rect-only landmark max (8x uint4)
    dim3 grid(32, 2, 16);                      // 2-row strips, co halves, batch
    conv_mma_kernel<<<grid, 512, SMEM_TOTAL>>>(bias, out);
}